// round 4
// baseline (speedup 1.0000x reference)
#include <cuda_runtime.h>

// Problem constants
#define NPTS 4096
#define DIM  64
#define TS   128          // block tile (i and j)
#define TT   8            // thread tile (i and j)
#define THREADS 256       // 16x16 threads
#define IBLOCKS (NPTS/TS) // 32
#define JSPLIT 32         // one j-tile per block -> 1024 blocks
#define LDS_PAD 4
#define ROWSTRIDE (TS + LDS_PAD)         // 132 floats
#define SMEM_FLOATS (2*DIM*ROWSTRIDE + 2*TS)
#define SMEM_BYTES  (SMEM_FLOATS * 4)    // 68608 B

// Scratch (device globals -- no allocation allowed)
__device__ float g_sq[NPTS];
__device__ float g_part[JSPLIT * NPTS];

// ---------- packed f32x2 helpers (FFMA2 only reachable via PTX) ----------
__device__ __forceinline__ unsigned long long pack2(float lo, float hi) {
    unsigned long long r;
    asm("mov.b64 %0, {%1, %2};" : "=l"(r) : "f"(lo), "f"(hi));
    return r;
}
__device__ __forceinline__ void unpack2(float& lo, float& hi, unsigned long long v) {
    asm("mov.b64 {%0, %1}, %2;" : "=f"(lo), "=f"(hi) : "l"(v));
}
__device__ __forceinline__ unsigned long long fma2(unsigned long long a,
                                                   unsigned long long b,
                                                   unsigned long long c) {
    unsigned long long d;
    asm("fma.rn.f32x2 %0, %1, %2, %3;" : "=l"(d) : "l"(a), "l"(b), "l"(c));
    return d;
}

// ---------- kernel 1: row squared norms ----------
__global__ void svr_sq(const float* __restrict__ feat) {
    int i = blockIdx.x * blockDim.x + threadIdx.x;
    if (i < NPTS) {
        const float4* f = reinterpret_cast<const float4*>(feat) + i * (DIM / 4);
        float s = 0.f;
#pragma unroll
        for (int k = 0; k < DIM / 4; k++) {
            float4 v = f[k];
            s = fmaf(v.x, v.x, s);
            s = fmaf(v.y, v.y, s);
            s = fmaf(v.z, v.z, s);
            s = fmaf(v.w, v.w, s);
        }
        g_sq[i] = s;
    }
}

// ---------- kernel 2: main RBF-kernel * alpha, one (i-tile, j-tile) per block ----------
__global__ __launch_bounds__(THREADS, 2)
void svr_main(const float* __restrict__ feat, const float* __restrict__ alpha) {
    extern __shared__ float sm[];
    float* si     = sm;                       // [DIM][ROWSTRIDE] i-tile, transposed
    float* sj     = si + DIM * ROWSTRIDE;     // [DIM][ROWSTRIDE] j-tile, transposed
    float* salpha = sj + DIM * ROWSTRIDE;     // [TS]
    float* ssqj   = salpha + TS;              // [TS]

    const int tid = threadIdx.x;
    const int tx  = tid & 15;
    const int ty  = tid >> 4;
    const int ibase = blockIdx.x * TS;
    const int jbase = blockIdx.y * TS;

    // Small scalar staging first so these LDGs overlap the big tile staging.
    if (tid < TS) {
        salpha[tid] = alpha[jbase + tid];
        ssqj[tid]   = g_sq[jbase + tid];
    }

    // Stage i-tile transposed: si[k][row] = feat[ibase+row][k]
    for (int idx = tid; idx < TS * (DIM / 4); idx += THREADS) {
        int row = idx & (TS - 1);
        int k4  = idx >> 7;
        float4 v = reinterpret_cast<const float4*>(feat)[(ibase + row) * (DIM / 4) + k4];
        int k = k4 * 4;
        si[(k + 0) * ROWSTRIDE + row] = v.x;
        si[(k + 1) * ROWSTRIDE + row] = v.y;
        si[(k + 2) * ROWSTRIDE + row] = v.z;
        si[(k + 3) * ROWSTRIDE + row] = v.w;
    }
    // Stage j-tile transposed
    for (int idx = tid; idx < TS * (DIM / 4); idx += THREADS) {
        int row = idx & (TS - 1);
        int k4  = idx >> 7;
        float4 v = reinterpret_cast<const float4*>(feat)[(jbase + row) * (DIM / 4) + k4];
        int k = k4 * 4;
        sj[(k + 0) * ROWSTRIDE + row] = v.x;
        sj[(k + 1) * ROWSTRIDE + row] = v.y;
        sj[(k + 2) * ROWSTRIDE + row] = v.z;
        sj[(k + 3) * ROWSTRIDE + row] = v.w;
    }

    const int irow = ibase + ty * TT;
    float sqi[TT], part[TT];
#pragma unroll
    for (int r = 0; r < TT; r++) {
        sqi[r]  = g_sq[irow + r];
        part[r] = 0.f;
    }
    __syncthreads();

    // 8x8 dot-product accumulation, packed as 4x8 f32x2.
    // Software-pipelined: LDS for step k+1 issued before FMA body of step k.
    unsigned long long acc[4][8];
#pragma unroll
    for (int r = 0; r < 4; r++)
#pragma unroll
        for (int c = 0; c < 8; c++) acc[r][c] = 0ull;

    const float* siBase = si + ty * TT;
    const float* sjBase = sj + tx * TT;

    float4 a0 = *reinterpret_cast<const float4*>(siBase);
    float4 a1 = *reinterpret_cast<const float4*>(siBase + 4);
    float4 b0 = *reinterpret_cast<const float4*>(sjBase);
    float4 b1 = *reinterpret_cast<const float4*>(sjBase + 4);

#pragma unroll 4
    for (int k = 0; k < DIM; k++) {
        float4 ca0 = a0, ca1 = a1, cb0 = b0, cb1 = b1;
        if (k + 1 < DIM) {
            const float* sik = siBase + (k + 1) * ROWSTRIDE;
            const float* sjk = sjBase + (k + 1) * ROWSTRIDE;
            a0 = *reinterpret_cast<const float4*>(sik);
            a1 = *reinterpret_cast<const float4*>(sik + 4);
            b0 = *reinterpret_cast<const float4*>(sjk);
            b1 = *reinterpret_cast<const float4*>(sjk + 4);
        }
        unsigned long long a2[4];
        a2[0] = pack2(ca0.x, ca0.y);
        a2[1] = pack2(ca0.z, ca0.w);
        a2[2] = pack2(ca1.x, ca1.y);
        a2[3] = pack2(ca1.z, ca1.w);
        float bv[8] = {cb0.x, cb0.y, cb0.z, cb0.w, cb1.x, cb1.y, cb1.z, cb1.w};
#pragma unroll
        for (int c = 0; c < 8; c++) {
            unsigned long long bb = pack2(bv[c], bv[c]);
#pragma unroll
            for (int r = 0; r < 4; r++) acc[r][c] = fma2(a2[r], bb, acc[r][c]);
        }
    }

    // Epilogue: d2 -> exp -> weighted accumulate
    const float inv2s2 = 0.02f;  // 1 / (2 * 5^2)
#pragma unroll
    for (int c = 0; c < 8; c++) {
        float aj  = salpha[tx * TT + c];
        float sj2 = ssqj[tx * TT + c];
#pragma unroll
        for (int r = 0; r < 4; r++) {
            float d0, d1;
            unpack2(d0, d1, acc[r][c]);
            float x0 = fmaxf(fmaf(-2.f, d0, sqi[2 * r] + sj2), 0.f);
            float x1 = fmaxf(fmaf(-2.f, d1, sqi[2 * r + 1] + sj2), 0.f);
            float w0 = __expf(-inv2s2 * x0);
            float w1 = __expf(-inv2s2 * x1);
            part[2 * r]     = fmaf(w0, aj, part[2 * r]);
            part[2 * r + 1] = fmaf(w1, aj, part[2 * r + 1]);
        }
    }

    // Reduce over tx (shfl stays within each 16-lane half of the warp)
#pragma unroll
    for (int r = 0; r < TT; r++) {
        float v = part[r];
        v += __shfl_xor_sync(0xffffffffu, v, 8);
        v += __shfl_xor_sync(0xffffffffu, v, 4);
        v += __shfl_xor_sync(0xffffffffu, v, 2);
        v += __shfl_xor_sync(0xffffffffu, v, 1);
        if (tx == 0) g_part[blockIdx.y * NPTS + irow + r] = v;
    }
}

// ---------- kernel 3: reduce j-splits + bias ----------
__global__ void svr_final(const float* __restrict__ bias, float* __restrict__ out) {
    int i = blockIdx.x * blockDim.x + threadIdx.x;
    if (i < NPTS) {
        float s = bias[0];
#pragma unroll
        for (int p = 0; p < JSPLIT; p++) s += g_part[p * NPTS + i];
        out[i] = s;
    }
}

extern "C" void kernel_launch(void* const* d_in, const int* in_sizes, int n_in,
                              void* d_out, int out_size) {
    const float* feat  = (const float*)d_in[0];
    const float* alpha = (const float*)d_in[1];
    const float* bias  = (const float*)d_in[2];
    float* out = (float*)d_out;

    // Unconditional (no static guards allowed); not a stream op -> capture-safe.
    cudaFuncSetAttribute(svr_main, cudaFuncAttributeMaxDynamicSharedMemorySize,
                         SMEM_BYTES);

    svr_sq<<<NPTS / 256, 256>>>(feat);
    svr_main<<<dim3(IBLOCKS, JSPLIT), THREADS, SMEM_BYTES>>>(feat, alpha);
    svr_final<<<NPTS / 256, 256>>>(bias, out);
}

// round 5
// speedup vs baseline: 1.0415x; 1.0415x over previous
#include <cuda_runtime.h>

// Problem constants
#define NPTS 4096
#define DIM  64
#define TS   128          // block tile (i and j)
#define TT   8            // thread tile (i and j)
#define THREADS 256       // 16x16 threads
#define IBLOCKS (NPTS/TS) // 32
#define JSPLIT 32         // one j-tile per block -> 1024 blocks
#define LDS_PAD 4
#define ROWSTRIDE (TS + LDS_PAD)         // 132 floats
#define SMEM_FLOATS (2*DIM*ROWSTRIDE + 3*TS)
#define SMEM_BYTES  (SMEM_FLOATS * 4)    // 69120 B

// Scratch (device global -- no allocation allowed)
__device__ float g_part[JSPLIT * NPTS];

// ---------- packed f32x2 helpers ----------
__device__ __forceinline__ unsigned long long dup2(float v) {
    unsigned long long r;
    asm("mov.b64 %0, {%1, %1};" : "=l"(r) : "f"(v));
    return r;
}
__device__ __forceinline__ void unpack2(float& lo, float& hi, unsigned long long v) {
    asm("mov.b64 {%0, %1}, %2;" : "=f"(lo), "=f"(hi) : "l"(v));
}
__device__ __forceinline__ unsigned long long fma2(unsigned long long a,
                                                   unsigned long long b,
                                                   unsigned long long c) {
    unsigned long long d;
    asm("fma.rn.f32x2 %0, %1, %2, %3;" : "=l"(d) : "l"(a), "l"(b), "l"(c));
    return d;
}

// ---------- kernel 1: main RBF-kernel * alpha, one (i-tile, j-tile) per block ----------
__global__ __launch_bounds__(THREADS, 2)
void svr_main(const float* __restrict__ feat, const float* __restrict__ alpha) {
    extern __shared__ float sm[];
    float* si     = sm;                       // [DIM][ROWSTRIDE] i-tile, transposed
    float* sj     = si + DIM * ROWSTRIDE;     // [DIM][ROWSTRIDE] j-tile, transposed
    float* salpha = sj + DIM * ROWSTRIDE;     // [TS]
    float* ssqj   = salpha + TS;              // [TS]
    float* ssqi   = ssqj + TS;                // [TS]

    const int tid = threadIdx.x;
    const int tx  = tid & 15;
    const int ty  = tid >> 4;
    const int ibase = blockIdx.x * TS;
    const int jbase = blockIdx.y * TS;

    if (tid < TS) salpha[tid] = alpha[jbase + tid];

    // Stage i-tile transposed: si[k][row] = feat[ibase+row][k]
    for (int idx = tid; idx < TS * (DIM / 4); idx += THREADS) {
        int row = idx & (TS - 1);
        int k4  = idx >> 7;
        float4 v = reinterpret_cast<const float4*>(feat)[(ibase + row) * (DIM / 4) + k4];
        int k = k4 * 4;
        si[(k + 0) * ROWSTRIDE + row] = v.x;
        si[(k + 1) * ROWSTRIDE + row] = v.y;
        si[(k + 2) * ROWSTRIDE + row] = v.z;
        si[(k + 3) * ROWSTRIDE + row] = v.w;
    }
    // Stage j-tile transposed
    for (int idx = tid; idx < TS * (DIM / 4); idx += THREADS) {
        int row = idx & (TS - 1);
        int k4  = idx >> 7;
        float4 v = reinterpret_cast<const float4*>(feat)[(jbase + row) * (DIM / 4) + k4];
        int k = k4 * 4;
        sj[(k + 0) * ROWSTRIDE + row] = v.x;
        sj[(k + 1) * ROWSTRIDE + row] = v.y;
        sj[(k + 2) * ROWSTRIDE + row] = v.z;
        sj[(k + 3) * ROWSTRIDE + row] = v.w;
    }
    __syncthreads();

    // Fused row squared norms from staged tiles.
    // Threads 0..127 -> i rows, 128..255 -> j rows; per-k accesses are
    // consecutive across threads -> conflict-free.
    {
        int r = tid & (TS - 1);
        const float* base = (tid < TS) ? si : sj;
        float s = 0.f;
#pragma unroll
        for (int k = 0; k < DIM; k++) {
            float v = base[k * ROWSTRIDE + r];
            s = fmaf(v, v, s);
        }
        if (tid < TS) ssqi[r] = s; else ssqj[r] = s;
    }
    __syncthreads();

    const int irow = ibase + ty * TT;
    float sqi[TT], part[TT];
#pragma unroll
    for (int r = 0; r < TT; r++) {
        sqi[r]  = ssqi[ty * TT + r];
        part[r] = 0.f;
    }

    // 8x8 dot-product accumulation, packed as 4x8 f32x2.
    // a-side pairs come straight from LDS128 (already packed, no movs);
    // only the 8 b-duplications per k-step cost instructions.
    unsigned long long acc[4][8];
#pragma unroll
    for (int r = 0; r < 4; r++)
#pragma unroll
        for (int c = 0; c < 8; c++) acc[r][c] = 0ull;

    const float* siBase = si + ty * TT;
    const float* sjBase = sj + tx * TT;

    ulonglong2 A0 = *reinterpret_cast<const ulonglong2*>(siBase);
    ulonglong2 A1 = *reinterpret_cast<const ulonglong2*>(siBase + 4);
    float4 b0 = *reinterpret_cast<const float4*>(sjBase);
    float4 b1 = *reinterpret_cast<const float4*>(sjBase + 4);

#pragma unroll 4
    for (int k = 0; k < DIM; k++) {
        ulonglong2 cA0 = A0, cA1 = A1;
        float4 cb0 = b0, cb1 = b1;
        if (k + 1 < DIM) {
            const float* sik = siBase + (k + 1) * ROWSTRIDE;
            const float* sjk = sjBase + (k + 1) * ROWSTRIDE;
            A0 = *reinterpret_cast<const ulonglong2*>(sik);
            A1 = *reinterpret_cast<const ulonglong2*>(sik + 4);
            b0 = *reinterpret_cast<const float4*>(sjk);
            b1 = *reinterpret_cast<const float4*>(sjk + 4);
        }
        unsigned long long a2[4] = {cA0.x, cA0.y, cA1.x, cA1.y};
        float bv[8] = {cb0.x, cb0.y, cb0.z, cb0.w, cb1.x, cb1.y, cb1.z, cb1.w};
#pragma unroll
        for (int c = 0; c < 8; c++) {
            unsigned long long bb = dup2(bv[c]);
#pragma unroll
            for (int r = 0; r < 4; r++) acc[r][c] = fma2(a2[r], bb, acc[r][c]);
        }
    }

    // Epilogue: d2 -> exp -> weighted accumulate
    const float inv2s2 = 0.02f;  // 1 / (2 * 5^2)
#pragma unroll
    for (int c = 0; c < 8; c++) {
        float aj  = salpha[tx * TT + c];
        float sj2 = ssqj[tx * TT + c];
#pragma unroll
        for (int r = 0; r < 4; r++) {
            float d0, d1;
            unpack2(d0, d1, acc[r][c]);
            float x0 = fmaxf(fmaf(-2.f, d0, sqi[2 * r] + sj2), 0.f);
            float x1 = fmaxf(fmaf(-2.f, d1, sqi[2 * r + 1] + sj2), 0.f);
            float w0 = __expf(-inv2s2 * x0);
            float w1 = __expf(-inv2s2 * x1);
            part[2 * r]     = fmaf(w0, aj, part[2 * r]);
            part[2 * r + 1] = fmaf(w1, aj, part[2 * r + 1]);
        }
    }

    // Reduce over tx (shfl stays within each 16-lane half of the warp)
#pragma unroll
    for (int r = 0; r < TT; r++) {
        float v = part[r];
        v += __shfl_xor_sync(0xffffffffu, v, 8);
        v += __shfl_xor_sync(0xffffffffu, v, 4);
        v += __shfl_xor_sync(0xffffffffu, v, 2);
        v += __shfl_xor_sync(0xffffffffu, v, 1);
        if (tx == 0) g_part[blockIdx.y * NPTS + irow + r] = v;
    }
}

// ---------- kernel 2: reduce j-splits + bias ----------
__global__ void svr_final(const float* __restrict__ bias, float* __restrict__ out) {
    int i = blockIdx.x * blockDim.x + threadIdx.x;
    if (i < NPTS) {
        float s = bias[0];
#pragma unroll
        for (int p = 0; p < JSPLIT; p++) s += g_part[p * NPTS + i];
        out[i] = s;
    }
}

extern "C" void kernel_launch(void* const* d_in, const int* in_sizes, int n_in,
                              void* d_out, int out_size) {
    const float* feat  = (const float*)d_in[0];
    const float* alpha = (const float*)d_in[1];
    const float* bias  = (const float*)d_in[2];
    float* out = (float*)d_out;

    // Unconditional (no static guards allowed); not a stream op -> capture-safe.
    cudaFuncSetAttribute(svr_main, cudaFuncAttributeMaxDynamicSharedMemorySize,
                         SMEM_BYTES);

    svr_main<<<dim3(IBLOCKS, JSPLIT), THREADS, SMEM_BYTES>>>(feat, alpha);
    svr_final<<<NPTS / 256, 256>>>(bias, out);
}